// round 2
// baseline (speedup 1.0000x reference)
#include <cuda_runtime.h>
#include <cuda_bf16.h>
#include <cstdint>
#include <cmath>

// ---------------------------------------------------------------------------
// Problem constants
// ---------------------------------------------------------------------------
#define INV_TAU (1.0f / 0.07f)
static constexpr int D_DIM   = 256;     // feature dim (GEMM K)
static constexpr int NZ      = 512;     // B*L frames
static constexpr int MROWS   = 640;     // 5 M-tiles of 128 (512 z + 16 g + pad)
static constexpr int NCHUNKQ = 512;     // queue chunks of 256 rows (131072/256)
static constexpr int NCHUNKT = 514;     // + 2 chunks where B = z (sim_zz / sim_gz)
static constexpr int SMEM_BYTES = 65536 + 131072;   // A tile (64KB) + B tile (128KB)

// ---------------------------------------------------------------------------
// Scratch (device globals; allocation-free)
// ---------------------------------------------------------------------------
__device__ __nv_bfloat16 g_A[MROWS * D_DIM];     // pre-swizzled A (z/tau, g/tau)
__device__ float g_pmax[NCHUNKQ * MROWS];        // per-chunk row max
__device__ float g_psum[NCHUNKQ * MROWS];        // per-chunk row sumexp
__device__ float g_logits[MROWS * NZ];           // fp32 logits vs z columns
__device__ float g_lse[MROWS];                   // queue LSE per row
__device__ float g_cll[NZ];
__device__ float g_csm[NZ];
__device__ float g_cgl[16];

#define DEV_INLINE __device__ __forceinline__

DEV_INLINE uint32_t smem_u32(const void* p) {
    uint32_t a;
    asm("{ .reg .u64 t; cvta.to.shared.u64 t, %1; cvt.u32.u64 %0, t; }" : "=r"(a) : "l"(p));
    return a;
}

DEV_INLINE void ldsm_x4(uint32_t* r, uint32_t addr) {
    asm volatile("ldmatrix.sync.aligned.m8n8.x4.shared.b16 {%0,%1,%2,%3}, [%4];"
                 : "=r"(r[0]), "=r"(r[1]), "=r"(r[2]), "=r"(r[3]) : "r"(addr));
}

DEV_INLINE void mma16816(float* d, const uint32_t* a, uint32_t b0, uint32_t b1) {
    asm volatile(
        "mma.sync.aligned.m16n8k16.row.col.f32.bf16.bf16.f32 "
        "{%0,%1,%2,%3}, {%4,%5,%6,%7}, {%8,%9}, {%0,%1,%2,%3};"
        : "+f"(d[0]), "+f"(d[1]), "+f"(d[2]), "+f"(d[3])
        : "r"(a[0]), "r"(a[1]), "r"(a[2]), "r"(a[3]), "r"(b0), "r"(b1));
}

// log-domain accumulate: (m,s) += (m2,s2)   [s holds sum of exp(x-m)]
DEV_INLINE void lse_acc(float& m, float& s, float m2, float s2) {
    if (m2 == -INFINITY) return;
    if (m2 <= m) {
        s += s2 * __expf(m2 - m);
    } else {
        s = s * __expf(m - m2) + s2;
        m = m2;
    }
}
DEV_INLINE float logaddexp_f(float a, float b) {
    float mx = fmaxf(a, b);
    return mx + log1pf(__expf(-fabsf(a - b)));
}

// ---------------------------------------------------------------------------
// Kernel 1: build A (bf16, scaled by 1/tau, XOR-swizzled 512B rows)
//   layout: byte = row*512 + ((c/8 ^ (row&7))*16) + (c%8)*2
// ---------------------------------------------------------------------------
__global__ void prep_kernel(const float* __restrict__ zt, const float* __restrict__ gv) {
    int row = blockIdx.x;    // 0..639
    int c   = threadIdx.x;   // 0..255
    float v = 0.f;
    if (row < NZ)            v = zt[row * D_DIM + c] * INV_TAU;
    else if (row < NZ + 16)  v = gv[(row - NZ) * D_DIM + c] * INV_TAU;
    uint32_t off = (uint32_t)row * 512u + ((((uint32_t)c >> 3) ^ ((uint32_t)row & 7u)) << 4) + ((uint32_t)c & 7u) * 2u;
    *(__nv_bfloat16*)((char*)g_A + off) = __float2bfloat16_rn(v);
}

// ---------------------------------------------------------------------------
// Kernel 2: bf16 mma.sync GEMM + fused LSE / logits epilogue
//   grid = 514 CTAs x 256 threads (8 warps in a 2x4 row-col grid, warp tile 64x64)
//   chunks 0..511: B = queue rows [chunk*256, +256)  -> (max, sumexp) partials
//   chunks 512/513: B = z rows -> raw fp32 logits dump
// ---------------------------------------------------------------------------
__global__ void __launch_bounds__(256, 1)
gemm_kernel(const float* __restrict__ mq, const float* __restrict__ zt) {
    extern __shared__ __align__(16) char smem[];
    __shared__ float spm[128][4];
    __shared__ float sps[128][4];

    const int tid = threadIdx.x;
    const int l   = tid & 31;
    const int w   = tid >> 5;
    const int wr  = w >> 2;          // warp row (0,1) -> rows wr*64..+63
    const int wc  = w & 3;           // warp col (0..3) -> cols wc*64..+63
    const int chunk = blockIdx.x;
    const bool isq = (chunk < NCHUNKQ);

    const uint32_t sA = smem_u32(smem);
    const uint32_t sB = sA + 65536;
    char* pB = smem + 65536;

    // ---- B chunk: 256 rows x 256 cols fp32 -> bf16 swizzled SMEM ----
    const float4* bsrc = (const float4*)(isq ? (mq + (size_t)chunk * 65536)
                                             : (zt + (size_t)(chunk - NCHUNKQ) * 65536));
#pragma unroll
    for (int it = 0; it < 32; it++) {
        int i  = tid + it * 256;        // 0..8191 : 16B output chunks
        int r  = i >> 5;                // B row 0..255
        int c4 = i & 31;                // 16B chunk within row
        float4 f0 = bsrc[r * 64 + c4 * 2];
        float4 f1 = bsrc[r * 64 + c4 * 2 + 1];
        __nv_bfloat162 p0 = __floats2bfloat162_rn(f0.x, f0.y);
        __nv_bfloat162 p1 = __floats2bfloat162_rn(f0.z, f0.w);
        __nv_bfloat162 p2 = __floats2bfloat162_rn(f1.x, f1.y);
        __nv_bfloat162 p3 = __floats2bfloat162_rn(f1.z, f1.w);
        uint4 v;
        v.x = *reinterpret_cast<uint32_t*>(&p0);
        v.y = *reinterpret_cast<uint32_t*>(&p1);
        v.z = *reinterpret_cast<uint32_t*>(&p2);
        v.w = *reinterpret_cast<uint32_t*>(&p3);
        *(uint4*)(pB + (uint32_t)r * 512u + ((((uint32_t)c4 ^ ((uint32_t)r & 7u))) << 4)) = v;
    }

    // ---- per-lane ldmatrix base addresses ----
    const uint32_t sw = (uint32_t)(l & 7);
    uint32_t aBase[4];
#pragma unroll
    for (int mf = 0; mf < 4; mf++) {
        int arow = wr * 64 + mf * 16 + (l & 7) + 8 * ((l >> 3) & 1);
        aBase[mf] = sA + (uint32_t)arow * 512u;
    }
    uint32_t bBase[4];
#pragma unroll
    for (int jp = 0; jp < 4; jp++) {
        int brow = wc * 64 + jp * 16 + (l & 7) + 8 * (l >> 4);
        bBase[jp] = sB + (uint32_t)brow * 512u;
    }
    const uint32_t kcaSel = (uint32_t)(l >> 4);        // A: k-octet select
    const uint32_t kcbSel = (uint32_t)((l >> 3) & 1);  // B: k-octet select

    // =================== main tiles: mt = 0..3 (rows mt*128..+127) ===============
    for (int mt = 0; mt < 4; mt++) {
        __syncthreads();   // prior-tile SMEM reads + spm combine done
        {   // copy pre-swizzled A tile (64KB)
            const uint4* asrc = ((const uint4*)g_A) + mt * 4096;
            uint4* adst = (uint4*)smem;
#pragma unroll
            for (int it = 0; it < 16; it++) adst[tid + it * 256] = asrc[tid + it * 256];
        }
        __syncthreads();

        float d[4][8][4];
#pragma unroll
        for (int mf = 0; mf < 4; mf++)
#pragma unroll
            for (int nf = 0; nf < 8; nf++)
#pragma unroll
                for (int v = 0; v < 4; v++) d[mf][nf][v] = 0.f;

#pragma unroll 2
        for (int ks = 0; ks < 16; ks++) {
            uint32_t a[4][4], b[4][4];
            uint32_t offA = (((uint32_t)(2 * ks) + kcaSel) ^ sw) << 4;
            uint32_t offB = (((uint32_t)(2 * ks) + kcbSel) ^ sw) << 4;
#pragma unroll
            for (int mf = 0; mf < 4; mf++) ldsm_x4(a[mf], aBase[mf] + offA);
#pragma unroll
            for (int jp = 0; jp < 4; jp++) ldsm_x4(b[jp], bBase[jp] + offB);
#pragma unroll
            for (int mf = 0; mf < 4; mf++)
#pragma unroll
                for (int jp = 0; jp < 4; jp++) {
                    mma16816(d[mf][2 * jp],     a[mf], b[jp][0], b[jp][1]);
                    mma16816(d[mf][2 * jp + 1], a[mf], b[jp][2], b[jp][3]);
                }
        }

        if (isq) {
            // fused (max, sumexp) per row over this warp's 64 cols
#pragma unroll
            for (int mf = 0; mf < 4; mf++) {
                float mlo = -INFINITY, mhi = -INFINITY;
#pragma unroll
                for (int nf = 0; nf < 8; nf++) {
                    mlo = fmaxf(mlo, fmaxf(d[mf][nf][0], d[mf][nf][1]));
                    mhi = fmaxf(mhi, fmaxf(d[mf][nf][2], d[mf][nf][3]));
                }
                mlo = fmaxf(mlo, __shfl_xor_sync(0xffffffffu, mlo, 1));
                mlo = fmaxf(mlo, __shfl_xor_sync(0xffffffffu, mlo, 2));
                mhi = fmaxf(mhi, __shfl_xor_sync(0xffffffffu, mhi, 1));
                mhi = fmaxf(mhi, __shfl_xor_sync(0xffffffffu, mhi, 2));
                float slo = 0.f, shi = 0.f;
#pragma unroll
                for (int nf = 0; nf < 8; nf++) {
                    float t0 = d[mf][nf][0] - mlo; if (t0 > -20.f) slo += __expf(t0);
                    float t1 = d[mf][nf][1] - mlo; if (t1 > -20.f) slo += __expf(t1);
                    float t2 = d[mf][nf][2] - mhi; if (t2 > -20.f) shi += __expf(t2);
                    float t3 = d[mf][nf][3] - mhi; if (t3 > -20.f) shi += __expf(t3);
                }
                slo += __shfl_xor_sync(0xffffffffu, slo, 1);
                slo += __shfl_xor_sync(0xffffffffu, slo, 2);
                shi += __shfl_xor_sync(0xffffffffu, shi, 1);
                shi += __shfl_xor_sync(0xffffffffu, shi, 2);
                if ((l & 3) == 0) {
                    int trow = wr * 64 + mf * 16 + (l >> 2);
                    spm[trow][wc] = mlo;  sps[trow][wc] = slo;
                    spm[trow + 8][wc] = mhi;  sps[trow + 8][wc] = shi;
                }
            }
            __syncthreads();
            if (tid < 128) {
                float m = -INFINITY, s = 0.f;
#pragma unroll
                for (int v = 0; v < 4; v++) lse_acc(m, s, spm[tid][v], sps[tid][v]);
                g_pmax[chunk * MROWS + mt * 128 + tid] = m;
                g_psum[chunk * MROWS + mt * 128 + tid] = s;
            }
        } else {
            // dump fp32 logits vs z columns
            int colbase = (chunk - NCHUNKQ) * 256 + wc * 64;
#pragma unroll
            for (int mf = 0; mf < 4; mf++) {
                int row = mt * 128 + wr * 64 + mf * 16 + (l >> 2);
#pragma unroll
                for (int nf = 0; nf < 8; nf++) {
                    int col = colbase + nf * 8 + 2 * (l & 3);
                    *(float2*)&g_logits[(size_t)row * NZ + col] =
                        make_float2(d[mf][nf][0], d[mf][nf][1]);
                    *(float2*)&g_logits[(size_t)(row + 8) * NZ + col] =
                        make_float2(d[mf][nf][2], d[mf][nf][3]);
                }
            }
        }
    }

    // =================== slim tile: 16 g rows (global rows 512..527) =============
    __syncthreads();
    {
        const uint4* asrc = ((const uint4*)g_A) + 4 * 4096;
        uint4* adst = (uint4*)smem;
#pragma unroll
        for (int it = 0; it < 16; it++) adst[tid + it * 256] = asrc[tid + it * 256];
    }
    __syncthreads();

    if (wr == 0) {    // only warp row 0 (rows 0..15 of the tile are real)
        float d4[8][4];
#pragma unroll
        for (int nf = 0; nf < 8; nf++)
#pragma unroll
            for (int v = 0; v < 4; v++) d4[nf][v] = 0.f;

#pragma unroll 2
        for (int ks = 0; ks < 16; ks++) {
            uint32_t a[4], b[4][4];
            uint32_t offA = (((uint32_t)(2 * ks) + kcaSel) ^ sw) << 4;
            uint32_t offB = (((uint32_t)(2 * ks) + kcbSel) ^ sw) << 4;
            ldsm_x4(a, aBase[0] + offA);
#pragma unroll
            for (int jp = 0; jp < 4; jp++) ldsm_x4(b[jp], bBase[jp] + offB);
#pragma unroll
            for (int jp = 0; jp < 4; jp++) {
                mma16816(d4[2 * jp],     a, b[jp][0], b[jp][1]);
                mma16816(d4[2 * jp + 1], a, b[jp][2], b[jp][3]);
            }
        }

        if (isq) {
            float mlo = -INFINITY, mhi = -INFINITY;
#pragma unroll
            for (int nf = 0; nf < 8; nf++) {
                mlo = fmaxf(mlo, fmaxf(d4[nf][0], d4[nf][1]));
                mhi = fmaxf(mhi, fmaxf(d4[nf][2], d4[nf][3]));
            }
            mlo = fmaxf(mlo, __shfl_xor_sync(0xffffffffu, mlo, 1));
            mlo = fmaxf(mlo, __shfl_xor_sync(0xffffffffu, mlo, 2));
            mhi = fmaxf(mhi, __shfl_xor_sync(0xffffffffu, mhi, 1));
            mhi = fmaxf(mhi, __shfl_xor_sync(0xffffffffu, mhi, 2));
            float slo = 0.f, shi = 0.f;
#pragma unroll
            for (int nf = 0; nf < 8; nf++) {
                float t0 = d4[nf][0] - mlo; if (t0 > -20.f) slo += __expf(t0);
                float t1 = d4[nf][1] - mlo; if (t1 > -20.f) slo += __expf(t1);
                float t2 = d4[nf][2] - mhi; if (t2 > -20.f) shi += __expf(t2);
                float t3 = d4[nf][3] - mhi; if (t3 > -20.f) shi += __expf(t3);
            }
            slo += __shfl_xor_sync(0xffffffffu, slo, 1);
            slo += __shfl_xor_sync(0xffffffffu, slo, 2);
            shi += __shfl_xor_sync(0xffffffffu, shi, 1);
            shi += __shfl_xor_sync(0xffffffffu, shi, 2);
            if ((l & 3) == 0) {
                int trow = l >> 2;
                spm[trow][wc] = mlo;  sps[trow][wc] = slo;
                spm[trow + 8][wc] = mhi;  sps[trow + 8][wc] = shi;
            }
        } else {
            int colbase = (chunk - NCHUNKQ) * 256 + wc * 64;
            int row = 512 + (l >> 2);
#pragma unroll
            for (int nf = 0; nf < 8; nf++) {
                int col = colbase + nf * 8 + 2 * (l & 3);
                *(float2*)&g_logits[(size_t)row * NZ + col] = make_float2(d4[nf][0], d4[nf][1]);
                *(float2*)&g_logits[(size_t)(row + 8) * NZ + col] = make_float2(d4[nf][2], d4[nf][3]);
            }
        }
    }

    if (isq) {
        __syncthreads();
        if (tid < 16) {
            float m = -INFINITY, s = 0.f;
#pragma unroll
            for (int v = 0; v < 4; v++) lse_acc(m, s, spm[tid][v], sps[tid][v]);
            g_pmax[chunk * MROWS + 512 + tid] = m;
            g_psum[chunk * MROWS + 512 + tid] = s;
        }
    }
}

// ---------------------------------------------------------------------------
// Kernel 3: combine 512 chunk partials per row -> queue LSE
// ---------------------------------------------------------------------------
__global__ void reduce_kernel() {
    int row = blockIdx.x;      // 0..527
    int tid = threadIdx.x;     // 128
    float m = -INFINITY, s = 0.f;
    for (int c = tid; c < NCHUNKQ; c += 128)
        lse_acc(m, s, g_pmax[c * MROWS + row], g_psum[c * MROWS + row]);
    __shared__ float shm[128], shs[128];
    shm[tid] = m; shs[tid] = s;
    for (int off = 64; off; off >>= 1) {
        __syncthreads();
        if (tid < off) {
            float m1 = shm[tid], s1 = shs[tid];
            lse_acc(m1, s1, shm[tid + off], shs[tid + off]);
            shm[tid] = m1; shs[tid] = s1;
        }
    }
    if (tid == 0) g_lse[row] = shm[0] + logf(shs[0]);
}

// ---------------------------------------------------------------------------
// Kernel 4: masked LSE vs z-columns + combine + pos terms + smoothness
// ---------------------------------------------------------------------------
__global__ void final_kernel(const float* __restrict__ zt) {
    __shared__ float shm[256], shs[256];
    __shared__ float s_lneg;
    int r = blockIdx.x, tid = threadIdx.x;

    if (r < NZ) {
        int t = r & 31;
        const float* lrow = g_logits + (size_t)r * NZ;
        if (t != 31) {   // local-local anchor
            int c0 = tid, c1 = tid + 256;
            float v0 = lrow[c0]; if (c0 == r || c0 == r + 1) v0 = -INFINITY;
            float v1 = lrow[c1]; if (c1 == r || c1 == r + 1) v1 = -INFINITY;
            float m = -INFINITY, s = 0.f;
            lse_acc(m, s, v0, 1.f);
            lse_acc(m, s, v1, 1.f);
            shm[tid] = m; shs[tid] = s;
            for (int off = 128; off; off >>= 1) {
                __syncthreads();
                if (tid < off) {
                    float m1 = shm[tid], s1 = shs[tid];
                    lse_acc(m1, s1, shm[tid + off], shs[tid + off]);
                    shm[tid] = m1; shs[tid] = s1;
                }
            }
            if (tid == 0) {
                float lse_z   = shm[0] + logf(shs[0]);
                float lse_all = logaddexp_f(lse_z, g_lse[r]);
                float pos = lrow[r + 1];
                g_cll[r] = logaddexp_f(pos, lse_all) - pos;
            }
        } else if (tid == 0) {
            g_cll[r] = 0.f;
        }
        __syncthreads();
        if (t != 0) {   // smoothness ||z[r]-z[r-1]||^2
            float dd = zt[r * D_DIM + tid] - zt[(r - 1) * D_DIM + tid];
            shs[tid] = dd * dd;
            for (int off = 128; off; off >>= 1) {
                __syncthreads();
                if (tid < off) shs[tid] += shs[tid + off];
            }
            if (tid == 0) g_csm[r] = shs[0];
        } else if (tid == 0) {
            g_csm[r] = 0.f;
        }
    } else {             // global-local row for batch b
        int b = r - NZ;
        const float* lrow = g_logits + (size_t)r * NZ;
        int c0 = tid, c1 = tid + 256;
        float v0 = lrow[c0]; if ((c0 >> 5) == b) v0 = -INFINITY;
        float v1 = lrow[c1]; if ((c1 >> 5) == b) v1 = -INFINITY;
        float m = -INFINITY, s = 0.f;
        lse_acc(m, s, v0, 1.f);
        lse_acc(m, s, v1, 1.f);
        shm[tid] = m; shs[tid] = s;
        for (int off = 128; off; off >>= 1) {
            __syncthreads();
            if (tid < off) {
                float m1 = shm[tid], s1 = shs[tid];
                lse_acc(m1, s1, shm[tid + off], shs[tid + off]);
                shm[tid] = m1; shs[tid] = s1;
            }
        }
        if (tid == 0) s_lneg = logaddexp_f(shm[0] + logf(shs[0]), g_lse[r]);
        __syncthreads();
        if (tid < 32) {
            float pos = lrow[b * 32 + tid];
            float c = logaddexp_f(pos, s_lneg) - pos;
            for (int o = 16; o; o >>= 1) c += __shfl_down_sync(0xffffffffu, c, o);
            if (tid == 0) g_cgl[b] = c;
        }
    }
}

// ---------------------------------------------------------------------------
// Kernel 5: deterministic weighted sum -> d_out[0]
// ---------------------------------------------------------------------------
__global__ void sum_kernel(float* __restrict__ out) {
    __shared__ float sh[256];
    int tid = threadIdx.x;
    float a = 0.f;
    for (int i = tid; i < NZ; i += 256)
        a += g_cll[i] * (1.0f / 496.0f) + g_csm[i] * (0.1f / 496.0f);
    if (tid < 16) a += g_cgl[tid] * (0.5f / 512.0f);
    sh[tid] = a;
    for (int off = 128; off; off >>= 1) {
        __syncthreads();
        if (tid < off) sh[tid] += sh[tid + off];
    }
    if (tid == 0) out[0] = sh[0];
}

// ---------------------------------------------------------------------------
// Launch
// ---------------------------------------------------------------------------
extern "C" void kernel_launch(void* const* d_in, const int* in_sizes, int n_in,
                              void* d_out, int out_size) {
    (void)in_sizes; (void)n_in; (void)out_size;
    const float* zt = (const float*)d_in[0];   // [16,32,256]
    const float* gv = (const float*)d_in[1];   // [16,256]
    const float* mq = (const float*)d_in[3];   // [131072,256]

    cudaFuncSetAttribute((const void*)gemm_kernel,
                         cudaFuncAttributeMaxDynamicSharedMemorySize, SMEM_BYTES);

    prep_kernel<<<MROWS, 256>>>(zt, gv);
    gemm_kernel<<<NCHUNKT, 256, SMEM_BYTES>>>(mq, zt);
    reduce_kernel<<<528, 128>>>();
    final_kernel<<<528, 256>>>(zt);
    sum_kernel<<<1, 256>>>((float*)d_out);
}